// round 13
// baseline (speedup 1.0000x reference)
#include <cuda_runtime.h>
#include <cuda_fp16.h>
#include <cstdint>

#define NN 50000
#define EE 800000
#define HH 4

// -------- scratch (device globals, no allocations) --------
__device__ float g_pool[(size_t)NN * 256 * 3 + (size_t)NN * 8];
__device__ __half g_hf[(size_t)NN * 256];
__device__ int g_ipool[(size_t)NN * 3 + 1 + (size_t)EE];

// -------- small utility kernels --------
__global__ void zero_int(int* p, int n) {
    int t = blockIdx.x * blockDim.x + threadIdx.x;
    if (t < n) p[t] = 0;
}
__global__ void zero_f(float* p, int n) {
    int t = blockIdx.x * blockDim.x + threadIdx.x;
    if (t < n) p[t] = 0.f;
}
__global__ void hist_kernel(const int* __restrict__ dst, int* __restrict__ deg, int E) {
    int t = blockIdx.x * blockDim.x + threadIdx.x;
    if (t < E) atomicAdd(&deg[dst[t]], 1);
}
__global__ void scan_kernel(const int* __restrict__ deg, int* __restrict__ rowptr,
                            int* __restrict__ cursor, int N, int E) {
    __shared__ int sums[1024];
    int t = threadIdx.x;
    int chunk = (N + 1023) >> 10;
    int lo = t * chunk, hi = min(N, lo + chunk);
    int s = 0;
    for (int i = lo; i < hi; i++) s += deg[i];
    sums[t] = s;
    __syncthreads();
    for (int off = 1; off < 1024; off <<= 1) {
        int v = (t >= off) ? sums[t - off] : 0;
        __syncthreads();
        sums[t] += v;
        __syncthreads();
    }
    int run = (t == 0) ? 0 : sums[t - 1];
    for (int i = lo; i < hi; i++) { rowptr[i] = run; cursor[i] = run; run += deg[i]; }
    if (lo < N && hi == N) rowptr[N] = E;
}
__global__ void scatter_kernel(const int* __restrict__ src, const int* __restrict__ dst,
                               int* __restrict__ cursor, int* __restrict__ srcSorted, int E) {
    int t = blockIdx.x * blockDim.x + threadIdx.x;
    if (t >= E) return;
    int d = dst[t];
    int pos = atomicAdd(&cursor[d], 1);
    srcSorted[pos] = src[t];
}

// -------- tf32 tensor-core GEMM, double-buffered smem --------
// 128x128 block tile, 8 warps (2x4), 64x32 warp tile = 4x4 m16n8k8 frags.
// Always writes fp16 output (Ch). WF32: also write fp32 C.
// ATT: emit el/er partials via shuffle+atomicAdd (64-wide aligned heads).
__device__ __forceinline__ unsigned f2tf32(float f) {
    unsigned r;
    asm("cvt.rna.tf32.f32 %0, %1;" : "=r"(r) : "f"(f));
    return r;
}

#define SM_STRIDE 136

template <bool ATT, bool WF32>
__global__ __launch_bounds__(256) void gemm_tf32(const float* __restrict__ A,
                                                 const float* __restrict__ B,
                                                 float* __restrict__ C,
                                                 __half* __restrict__ Ch,
                                                 int M, int K, int Ncols,
                                                 const float* __restrict__ al,
                                                 const float* __restrict__ ar,
                                                 float* __restrict__ el,
                                                 float* __restrict__ er) {
    __shared__ unsigned As[2][16][SM_STRIDE];
    __shared__ unsigned Bs[2][16][SM_STRIDE];
    int tid = threadIdx.x;
    int warp = tid >> 5, lane = tid & 31;
    int gid = lane >> 2, tig = lane & 3;
    int warp_m = warp >> 2, warp_n = warp & 3;
    int rowBase = blockIdx.y * 128;
    int colBase = blockIdx.x * 128;

    int ar_ = tid >> 1;
    int ak = (tid & 1) * 8;
    int br = tid >> 4;
    int bc = (tid & 15) * 8;

    int gr = rowBase + ar_;
    bool aOk = (gr < M);
    int gc = colBase + bc;
    bool bFull = (gc + 7 < Ncols);

    const float* aBase = A + (size_t)gr * K + ak;
    const float* bBase = B + (size_t)br * Ncols + gc;

    float acc[4][4][4];
#pragma unroll
    for (int i = 0; i < 4; i++)
#pragma unroll
        for (int j = 0; j < 4; j++)
#pragma unroll
            for (int c = 0; c < 4; c++) acc[i][j][c] = 0.f;

    const int P = K >> 4;
    float ra[8], rb[8];

    auto loadPanel = [&](int p, float* la, float* lb) {
        const float* ap = aBase + p * 16;
        const float* bp = bBase + (size_t)p * 16 * Ncols;
        if (aOk) {
            float4 a0 = *reinterpret_cast<const float4*>(ap);
            float4 a1 = *reinterpret_cast<const float4*>(ap + 4);
            la[0] = a0.x; la[1] = a0.y; la[2] = a0.z; la[3] = a0.w;
            la[4] = a1.x; la[5] = a1.y; la[6] = a1.z; la[7] = a1.w;
        } else {
#pragma unroll
            for (int i = 0; i < 8; i++) la[i] = 0.f;
        }
        if (bFull) {
            float4 b0 = *reinterpret_cast<const float4*>(bp);
            float4 b1 = *reinterpret_cast<const float4*>(bp + 4);
            lb[0] = b0.x; lb[1] = b0.y; lb[2] = b0.z; lb[3] = b0.w;
            lb[4] = b1.x; lb[5] = b1.y; lb[6] = b1.z; lb[7] = b1.w;
        } else {
#pragma unroll
            for (int j = 0; j < 8; j++)
                lb[j] = (gc + j < Ncols) ? bp[j] : 0.f;
        }
    };

    // prologue: panel 0 -> smem[0]
    loadPanel(0, ra, rb);
#pragma unroll
    for (int i = 0; i < 8; i++) As[0][ak + i][ar_] = f2tf32(ra[i]);
#pragma unroll
    for (int j = 0; j < 8; j++) Bs[0][br][bc + j] = f2tf32(rb[j]);
    __syncthreads();

    for (int p = 0; p < P; p++) {
        int cur = p & 1, nxt = cur ^ 1;
        // prefetch next panel (LDG in flight during compute)
        if (p + 1 < P) loadPanel(p + 1, ra, rb);

        // compute from smem[cur]
#pragma unroll
        for (int ks = 0; ks < 2; ks++) {
            int k0 = ks * 8;
            unsigned af[4][4], bf[4][2];
#pragma unroll
            for (int mi = 0; mi < 4; mi++) {
                int mB = warp_m * 64 + mi * 16;
                af[mi][0] = As[cur][k0 + tig][mB + gid];
                af[mi][1] = As[cur][k0 + tig][mB + gid + 8];
                af[mi][2] = As[cur][k0 + tig + 4][mB + gid];
                af[mi][3] = As[cur][k0 + tig + 4][mB + gid + 8];
            }
#pragma unroll
            for (int ni = 0; ni < 4; ni++) {
                int nB = warp_n * 32 + ni * 8;
                bf[ni][0] = Bs[cur][k0 + tig][nB + gid];
                bf[ni][1] = Bs[cur][k0 + tig + 4][nB + gid];
            }
#pragma unroll
            for (int mi = 0; mi < 4; mi++)
#pragma unroll
                for (int ni = 0; ni < 4; ni++) {
                    asm volatile(
                        "mma.sync.aligned.m16n8k8.row.col.f32.tf32.tf32.f32 "
                        "{%0,%1,%2,%3}, {%4,%5,%6,%7}, {%8,%9}, {%0,%1,%2,%3};\n"
                        : "+f"(acc[mi][ni][0]), "+f"(acc[mi][ni][1]),
                          "+f"(acc[mi][ni][2]), "+f"(acc[mi][ni][3])
                        : "r"(af[mi][0]), "r"(af[mi][1]), "r"(af[mi][2]), "r"(af[mi][3]),
                          "r"(bf[ni][0]), "r"(bf[ni][1]));
                }
        }

        if (p + 1 < P) {
#pragma unroll
            for (int i = 0; i < 8; i++) As[nxt][ak + i][ar_] = f2tf32(ra[i]);
#pragma unroll
            for (int j = 0; j < 8; j++) Bs[nxt][br][bc + j] = f2tf32(rb[j]);
            __syncthreads();
        }
    }

    // store outputs
#pragma unroll
    for (int mi = 0; mi < 4; mi++) {
        int r0 = rowBase + warp_m * 64 + mi * 16 + gid;
#pragma unroll
        for (int ni = 0; ni < 4; ni++) {
            int c0 = colBase + warp_n * 32 + ni * 8 + tig * 2;
            if (c0 < Ncols) {
                if (r0 < M) {
                    *reinterpret_cast<__half2*>(&Ch[(size_t)r0 * Ncols + c0]) =
                        __floats2half2_rn(acc[mi][ni][0], acc[mi][ni][1]);
                    if (WF32)
                        *reinterpret_cast<float2*>(&C[(size_t)r0 * Ncols + c0]) =
                            make_float2(acc[mi][ni][0], acc[mi][ni][1]);
                }
                if (r0 + 8 < M) {
                    *reinterpret_cast<__half2*>(&Ch[(size_t)(r0 + 8) * Ncols + c0]) =
                        __floats2half2_rn(acc[mi][ni][2], acc[mi][ni][3]);
                    if (WF32)
                        *reinterpret_cast<float2*>(&C[(size_t)(r0 + 8) * Ncols + c0]) =
                            make_float2(acc[mi][ni][2], acc[mi][ni][3]);
                }
            }
        }
    }

    // fused el/er partials (heads 64 cols wide; warp's cols lie in one head)
    if (ATT) {
        int h = (colBase + warp_n * 32) >> 6;
#pragma unroll
        for (int mi = 0; mi < 4; mi++) {
            float pl0 = 0.f, pl1 = 0.f, pr0 = 0.f, pr1 = 0.f;
#pragma unroll
            for (int ni = 0; ni < 4; ni++) {
#pragma unroll
                for (int j = 0; j < 2; j++) {
                    int cw = (colBase + warp_n * 32 + ni * 8 + tig * 2 + j) & 63;
                    float av = al[h * 64 + cw];
                    float rv = ar[h * 64 + cw];
                    pl0 += acc[mi][ni][j] * av;
                    pr0 += acc[mi][ni][j] * rv;
                    pl1 += acc[mi][ni][2 + j] * av;
                    pr1 += acc[mi][ni][2 + j] * rv;
                }
            }
#pragma unroll
            for (int o = 1; o <= 2; o <<= 1) {
                pl0 += __shfl_xor_sync(0xffffffffu, pl0, o);
                pr0 += __shfl_xor_sync(0xffffffffu, pr0, o);
                pl1 += __shfl_xor_sync(0xffffffffu, pl1, o);
                pr1 += __shfl_xor_sync(0xffffffffu, pr1, o);
            }
            if (tig == 0) {
                int r0 = rowBase + warp_m * 64 + mi * 16 + gid;
                if (r0 < M) {
                    atomicAdd(&el[r0 * 4 + h], pl0);
                    atomicAdd(&er[r0 * 4 + h], pr0);
                }
                if (r0 + 8 < M) {
                    atomicAdd(&el[(r0 + 8) * 4 + h], pl1);
                    atomicAdd(&er[(r0 + 8) * 4 + h], pr1);
                }
            }
        }
    }
}

// -------- el/er for layer 2 (D=40, unaligned heads) — fp32 feat --------
__global__ void el_er_kernel(const float* __restrict__ feat,
                             const float* __restrict__ al, const float* __restrict__ ar,
                             float* __restrict__ el, float* __restrict__ er,
                             int N, int D) {
    int w = (blockIdx.x * blockDim.x + threadIdx.x) >> 5;
    int lane = threadIdx.x & 31;
    if (w >= N * HH) return;
    int n = w / HH, h = w - n * HH;
    const float* f = feat + (size_t)n * HH * D + h * D;
    float sl = 0.f, sr = 0.f;
    for (int d = lane; d < D; d += 32) {
        float fv = f[d];
        sl += fv * al[h * D + d];
        sr += fv * ar[h * D + d];
    }
#pragma unroll
    for (int o = 16; o; o >>= 1) {
        sl += __shfl_down_sync(0xffffffffu, sl, o);
        sr += __shfl_down_sync(0xffffffffu, sr, o);
    }
    if (lane == 0) { el[w] = sl; er[w] = sr; }
}

// 8 fp16 channels (uint4) fma into fp32 acc
__device__ __forceinline__ void hf8_fma(float* acc, uint4 u, float ee) {
    float2 f;
    f = __half22float2(*reinterpret_cast<__half2*>(&u.x));
    acc[0] += ee * f.x; acc[1] += ee * f.y;
    f = __half22float2(*reinterpret_cast<__half2*>(&u.y));
    acc[2] += ee * f.x; acc[3] += ee * f.y;
    f = __half22float2(*reinterpret_cast<__half2*>(&u.z));
    acc[4] += ee * f.x; acc[5] += ee * f.y;
    f = __half22float2(*reinterpret_cast<__half2*>(&u.w));
    acc[6] += ee * f.x; acc[7] += ee * f.y;
}

// -------- fused softmax + aggregation: one warp per dst node --------
// fp16 feature gather (8 channels/lane via LDG.128), fp32 accumulate.
// MODE 0: D=64, all 32 lanes, out[d,256] = elu(acc/den + bias)
// MODE 1: D=40, lanes 0..19, out = logits[d,40] = mean_h(acc/den + bias)
template <int D, int MODE>
__global__ __launch_bounds__(256) void gat_aggregate(
    const int* __restrict__ rowptr, const int* __restrict__ srcS,
    const float* __restrict__ el, const float* __restrict__ er,
    const __half* __restrict__ hfeat, const float* __restrict__ bias,
    float* __restrict__ out, int N) {
    constexpr int HD = 4 * D;
    __shared__ float sEE[8][4][32];
    __shared__ int sSrc[8][32];
    __shared__ float sOut[MODE == 1 ? 8 : 1][MODE == 1 ? 160 : 1];
    int wl = threadIdx.x >> 5, lane = threadIdx.x & 31;
    int d = blockIdx.x * 8 + wl;
    if (d >= N) return;
    int begin = rowptr[d], end = rowptr[d + 1];

    float4 erv = *reinterpret_cast<const float4*>(&er[d * 4]);
    float er4[4] = {erv.x, erv.y, erv.z, erv.w};

    float m[4] = {-1e30f, -1e30f, -1e30f, -1e30f};
    for (int i = begin + lane; i < end; i += 32) {
        int s = srcS[i];
        float4 e4 = *reinterpret_cast<const float4*>(&el[s * 4]);
        float v;
        v = e4.x + er4[0]; v = v > 0.f ? v : 0.2f * v; m[0] = fmaxf(m[0], v);
        v = e4.y + er4[1]; v = v > 0.f ? v : 0.2f * v; m[1] = fmaxf(m[1], v);
        v = e4.z + er4[2]; v = v > 0.f ? v : 0.2f * v; m[2] = fmaxf(m[2], v);
        v = e4.w + er4[3]; v = v > 0.f ? v : 0.2f * v; m[3] = fmaxf(m[3], v);
    }
#pragma unroll
    for (int h = 0; h < 4; h++)
#pragma unroll
        for (int o = 16; o; o >>= 1)
            m[h] = fmaxf(m[h], __shfl_xor_sync(0xffffffffu, m[h], o));

    float acc[8];
#pragma unroll
    for (int j = 0; j < 8; j++) acc[j] = 0.f;
    float den[4] = {0.f, 0.f, 0.f, 0.f};

    const int h = (MODE == 0) ? (lane >> 3) : (lane / 5);
    const bool active = (MODE == 0) ? true : (lane < 20);
    const int cOff = lane * 8;

    for (int base = begin; base < end; base += 32) {
        int cnt = min(32, end - base);
        if (lane < cnt) {
            int s = srcS[base + lane];
            sSrc[wl][lane] = s;
            float4 e4 = *reinterpret_cast<const float4*>(&el[s * 4]);
            float v, ee;
            v = e4.x + er4[0]; v = v > 0.f ? v : 0.2f * v; ee = __expf(v - m[0]); den[0] += ee; sEE[wl][0][lane] = ee;
            v = e4.y + er4[1]; v = v > 0.f ? v : 0.2f * v; ee = __expf(v - m[1]); den[1] += ee; sEE[wl][1][lane] = ee;
            v = e4.z + er4[2]; v = v > 0.f ? v : 0.2f * v; ee = __expf(v - m[2]); den[2] += ee; sEE[wl][2][lane] = ee;
            v = e4.w + er4[3]; v = v > 0.f ? v : 0.2f * v; ee = __expf(v - m[3]); den[3] += ee; sEE[wl][3][lane] = ee;
        }
        __syncwarp();

        if (active) {
            int t = 0;
            for (; t + 3 < cnt; t += 4) {
                int s0 = sSrc[wl][t], s1 = sSrc[wl][t + 1], s2 = sSrc[wl][t + 2], s3 = sSrc[wl][t + 3];
                uint4 u0 = *reinterpret_cast<const uint4*>(hfeat + (size_t)s0 * HD + cOff);
                uint4 u1 = *reinterpret_cast<const uint4*>(hfeat + (size_t)s1 * HD + cOff);
                uint4 u2 = *reinterpret_cast<const uint4*>(hfeat + (size_t)s2 * HD + cOff);
                uint4 u3 = *reinterpret_cast<const uint4*>(hfeat + (size_t)s3 * HD + cOff);
                hf8_fma(acc, u0, sEE[wl][h][t]);
                hf8_fma(acc, u1, sEE[wl][h][t + 1]);
                hf8_fma(acc, u2, sEE[wl][h][t + 2]);
                hf8_fma(acc, u3, sEE[wl][h][t + 3]);
            }
            for (; t < cnt; t++) {
                int s0 = sSrc[wl][t];
                uint4 u0 = *reinterpret_cast<const uint4*>(hfeat + (size_t)s0 * HD + cOff);
                hf8_fma(acc, u0, sEE[wl][h][t]);
            }
        }
        __syncwarp();
    }

#pragma unroll
    for (int hh = 0; hh < 4; hh++) {
#pragma unroll
        for (int o = 16; o; o >>= 1)
            den[hh] += __shfl_xor_sync(0xffffffffu, den[hh], o);
        den[hh] = fmaxf(den[hh], 1e-9f);
    }

    if constexpr (MODE == 0) {
        float inv = 1.f / den[h];
        float o[8];
#pragma unroll
        for (int j = 0; j < 8; j++) {
            float v = acc[j] * inv + bias[cOff + j];
            o[j] = v > 0.f ? v : expm1f(v);
        }
        float* op = out + (size_t)d * 256 + cOff;
        *reinterpret_cast<float4*>(op) = make_float4(o[0], o[1], o[2], o[3]);
        *reinterpret_cast<float4*>(op + 4) = make_float4(o[4], o[5], o[6], o[7]);
    } else {
        if (active) {
            float inv = 1.f / den[h];
#pragma unroll
            for (int j = 0; j < 8; j++)
                sOut[wl][cOff + j] = acc[j] * inv + bias[cOff + j];
        }
        __syncwarp();
        float* lg = out + (size_t)d * 40;
        {
            int c = lane;
            lg[c] = 0.25f * (sOut[wl][c] + sOut[wl][40 + c] + sOut[wl][80 + c] + sOut[wl][120 + c]);
        }
        if (lane < 8) {
            int c = 32 + lane;
            lg[c] = 0.25f * (sOut[wl][c] + sOut[wl][40 + c] + sOut[wl][80 + c] + sOut[wl][120 + c]);
        }
    }
}

// ---------------------------------------------------------------
extern "C" void kernel_launch(void* const* d_in, const int* in_sizes, int n_in,
                              void* d_out, int out_size) {
    const float* x  = (const float*)d_in[0];
    const int*   ei = (const int*)d_in[1];
    const float* W0  = (const float*)d_in[2];
    const float* al0 = (const float*)d_in[3];
    const float* ar0 = (const float*)d_in[4];
    const float* b0  = (const float*)d_in[5];
    const float* W1  = (const float*)d_in[6];
    const float* al1 = (const float*)d_in[7];
    const float* ar1 = (const float*)d_in[8];
    const float* b1  = (const float*)d_in[9];
    const float* W2  = (const float*)d_in[10];
    const float* al2 = (const float*)d_in[11];
    const float* ar2 = (const float*)d_in[12];
    const float* b2  = (const float*)d_in[13];

    int E = in_sizes[1] / 2;
    int N = in_sizes[0] / 256;
    const int* src = ei;
    const int* dst = ei + E;

    void* pv = nullptr;
    cudaGetSymbolAddress(&pv, g_pool);
    float* pool = (float*)pv;
    float* feat = pool;                              // fp32 feat (layer 2 only)
    float* bufA = feat + (size_t)NN * 256;
    float* bufB = bufA + (size_t)NN * 256;
    float* el   = bufB + (size_t)NN * 256;
    float* er   = el + (size_t)NN * 4;

    void* hv = nullptr;
    cudaGetSymbolAddress(&hv, g_hf);
    __half* hfeat = (__half*)hv;

    void* iv = nullptr;
    cudaGetSymbolAddress(&iv, g_ipool);
    int* rowptr = (int*)iv;
    int* deg    = rowptr + NN + 1;
    int* cursor = deg + NN;
    int* srcS   = cursor + NN;

    const int TB = 256;
    auto blocks = [](long n, int tb) { return (int)((n + tb - 1) / tb); };

    // ---- build CSR (by dst) ----
    zero_int<<<blocks(N, TB), TB>>>(deg, N);
    hist_kernel<<<blocks(E, TB), TB>>>(dst, deg, E);
    scan_kernel<<<1, 1024>>>(deg, rowptr, cursor, N, E);
    scatter_kernel<<<blocks(E, TB), TB>>>(src, dst, cursor, srcS, E);

    int aggBlocks = (N + 7) / 8;
    int gy = (N + 127) / 128;

    // ---- layer 0 ----
    zero_f<<<blocks((long)N * 8, TB), TB>>>(el, N * 8);
    gemm_tf32<true, false><<<dim3(2, gy), 256>>>(x, W0, nullptr, hfeat, N, 256, 256, al0, ar0, el, er);
    gat_aggregate<64, 0><<<aggBlocks, 256>>>(rowptr, srcS, el, er, hfeat, b0, bufA, N);
    // ---- layer 1 ----
    zero_f<<<blocks((long)N * 8, TB), TB>>>(el, N * 8);
    gemm_tf32<true, false><<<dim3(2, gy), 256>>>(bufA, W1, nullptr, hfeat, N, 256, 256, al1, ar1, el, er);
    gat_aggregate<64, 0><<<aggBlocks, 256>>>(rowptr, srcS, el, er, hfeat, b1, bufB, N);
    // ---- layer 2 (HD=160) ----
    gemm_tf32<false, true><<<dim3(2, gy), 256>>>(bufB, W2, feat, hfeat, N, 256, 160, nullptr, nullptr, nullptr, nullptr);
    el_er_kernel<<<blocks((long)N * HH * 32, TB), TB>>>(feat, al2, ar2, el, er, N, 40);
    gat_aggregate<40, 1><<<aggBlocks, 256>>>(rowptr, srcS, el, er, hfeat, b2, (float*)d_out, N);
}

// round 14
// speedup vs baseline: 1.2272x; 1.2272x over previous
#include <cuda_runtime.h>
#include <cuda_fp16.h>
#include <cstdint>

#define NN 50000
#define EE 800000
#define HH 4

// -------- scratch (device globals, no allocations) --------
// halves: hfeat NN*256 | bufA NN*256 | bufB NN*256
__device__ __half g_hf[(size_t)NN * 256 * 3];
// floats: feat(NN*256, fp32 copy for layer-2 el_er) | el NN*4 | er NN*4
__device__ float g_pool[(size_t)NN * 256 + (size_t)NN * 8];
// ints: rowptr NN+1 | deg NN | cursor NN | srcS EE | gmax 4
__device__ int g_ipool[(size_t)NN * 3 + 1 + (size_t)EE + 4];

__device__ __forceinline__ unsigned fkey(float f) {
    unsigned b = __float_as_uint(f);
    return (b & 0x80000000u) ? ~b : (b | 0x80000000u);
}
__device__ __forceinline__ float fdecode(unsigned k) {
    unsigned b = (k & 0x80000000u) ? (k ^ 0x80000000u) : ~k;
    return __uint_as_float(b);
}

// -------- small utility kernels --------
__global__ void zero_int(int* p, int n) {
    int t = blockIdx.x * blockDim.x + threadIdx.x;
    if (t < n) p[t] = 0;
}
// zero el+er (n floats) and gmax keys
__global__ void zero_att(float* p, unsigned* gmax, int n) {
    int t = blockIdx.x * blockDim.x + threadIdx.x;
    if (t < n) p[t] = 0.f;
    if (t < 4) gmax[t] = 0u;
}
__global__ void hist_kernel(const int* __restrict__ dst, int* __restrict__ deg, int E) {
    int t = blockIdx.x * blockDim.x + threadIdx.x;
    if (t < E) atomicAdd(&deg[dst[t]], 1);
}
__global__ void scan_kernel(const int* __restrict__ deg, int* __restrict__ rowptr,
                            int* __restrict__ cursor, int N, int E) {
    __shared__ int sums[1024];
    int t = threadIdx.x;
    int chunk = (N + 1023) >> 10;
    int lo = t * chunk, hi = min(N, lo + chunk);
    int s = 0;
    for (int i = lo; i < hi; i++) s += deg[i];
    sums[t] = s;
    __syncthreads();
    for (int off = 1; off < 1024; off <<= 1) {
        int v = (t >= off) ? sums[t - off] : 0;
        __syncthreads();
        sums[t] += v;
        __syncthreads();
    }
    int run = (t == 0) ? 0 : sums[t - 1];
    for (int i = lo; i < hi; i++) { rowptr[i] = run; cursor[i] = run; run += deg[i]; }
    if (lo < N && hi == N) rowptr[N] = E;
}
__global__ void scatter_kernel(const int* __restrict__ src, const int* __restrict__ dst,
                               int* __restrict__ cursor, int* __restrict__ srcSorted, int E) {
    int t = blockIdx.x * blockDim.x + threadIdx.x;
    if (t >= E) return;
    int d = dst[t];
    int pos = atomicAdd(&cursor[d], 1);
    srcSorted[pos] = src[t];
}

// global per-head max of el (block reduce -> 4 atomics per block)
__global__ void gmax_kernel(const float* __restrict__ el, unsigned* __restrict__ gmax, int n4) {
    float mx = -3e38f;
    int stride = gridDim.x * blockDim.x;   // multiple of 4
    for (int i = blockIdx.x * blockDim.x + threadIdx.x; i < n4; i += stride)
        mx = fmaxf(mx, el[i]);
    int h = threadIdx.x & 3;
#pragma unroll
    for (int o = 4; o < 32; o <<= 1)
        mx = fmaxf(mx, __shfl_xor_sync(0xffffffffu, mx, o));
    __shared__ unsigned sm[4];
    if (threadIdx.x < 4) sm[threadIdx.x] = 0u;
    __syncthreads();
    if ((threadIdx.x & 31) < 4) atomicMax(&sm[h], fkey(mx));
    __syncthreads();
    if (threadIdx.x < 4) atomicMax(&gmax[threadIdx.x], sm[threadIdx.x]);
}

// -------- fp16 HMMA GEMM, double-buffered, ldmatrix --------
// 128x128 block tile, 8 warps (2x4), 64x32 warp tile = 4x4 m16n8k16 frags.
// A,B converted to fp16 at smem store (A may already be fp16: AHALF).
// Writes fp16 Ch always; WF32: also fp32 C. ATT: fused el/er partials.
__device__ __forceinline__ void ldmA4(unsigned& r0, unsigned& r1, unsigned& r2, unsigned& r3, unsigned a) {
    asm volatile("ldmatrix.sync.aligned.m8n8.x4.shared.b16 {%0,%1,%2,%3}, [%4];"
                 : "=r"(r0), "=r"(r1), "=r"(r2), "=r"(r3) : "r"(a));
}
__device__ __forceinline__ void ldmBT4(unsigned& r0, unsigned& r1, unsigned& r2, unsigned& r3, unsigned a) {
    asm volatile("ldmatrix.sync.aligned.m8n8.x4.trans.shared.b16 {%0,%1,%2,%3}, [%4];"
                 : "=r"(r0), "=r"(r1), "=r"(r2), "=r"(r3) : "r"(a));
}

template <bool ATT, bool WF32, bool AHALF>
__global__ __launch_bounds__(256) void gemm_fp16(const float* __restrict__ Af,
                                                 const __half* __restrict__ Ah,
                                                 const float* __restrict__ B,
                                                 float* __restrict__ C,
                                                 __half* __restrict__ Ch,
                                                 int M, int K, int Ncols,
                                                 const float* __restrict__ al,
                                                 const float* __restrict__ ar,
                                                 float* __restrict__ el,
                                                 float* __restrict__ er) {
    // per-buffer layout: A tile 128x16 half (4096 B) | B tile 16x128 half (4096 B)
    __shared__ __align__(16) unsigned char smc[2][8192];
    unsigned smBase = (unsigned)__cvta_generic_to_shared(&smc[0][0]);

    int tid = threadIdx.x;
    int warp = tid >> 5, lane = tid & 31;
    int gid = lane >> 2, tig = lane & 3;
    int warp_m = warp >> 2, warp_n = warp & 3;
    int rowBase = blockIdx.y * 128;
    int colBase = blockIdx.x * 128;

    // global->smem mapping
    int ar_ = tid >> 1;              // A row 0..127
    int ak = (tid & 1) * 8;          // 0 / 8
    int br = tid >> 4;               // B k-row 0..15
    int bc = (tid & 15) * 8;         // B col 0..120

    int gr = rowBase + ar_;
    bool aOk = (gr < M);
    int gc = colBase + bc;
    bool bFull = (gc + 7 < Ncols);

    const float*  aBaseF = Af ? (Af + (size_t)gr * K + ak) : nullptr;
    const __half* aBaseH = Ah ? (Ah + (size_t)gr * K + ak) : nullptr;
    const float*  bBase  = B + (size_t)br * Ncols + gc;

    // swizzled STS offsets
    const int aSts = ((ar_ * 32 + ak * 2) ^ (((ar_ >> 2) & 1) << 4));
    const int bSts = 4096 + ((br * 256 + bc * 2) ^ ((br & 7) << 4));

    // ldmatrix per-lane offsets
    int lt = lane >> 3, lr = lane & 7;
    unsigned aOff[4];
#pragma unroll
    for (int mi = 0; mi < 4; mi++) {
        int m = warp_m * 64 + mi * 16 + (lt & 1) * 8 + lr;
        int kk = (lt >> 1) * 8;
        aOff[mi] = (unsigned)((m * 32 + kk * 2) ^ (((m >> 2) & 1) << 4));
    }
    unsigned bOff[2];
#pragma unroll
    for (int bi = 0; bi < 2; bi++) {
        int k = (lt & 1) * 8 + lr;
        int n = warp_n * 32 + bi * 16 + (lt >> 1) * 8;
        bOff[bi] = (unsigned)(4096 + ((k * 256 + n * 2) ^ ((k & 7) << 4)));
    }

    float acc[4][4][4];
#pragma unroll
    for (int i = 0; i < 4; i++)
#pragma unroll
        for (int j = 0; j < 4; j++)
#pragma unroll
            for (int c = 0; c < 4; c++) acc[i][j][c] = 0.f;

    const int P = K >> 4;
    uint4 stA;     // 8 halves of A panel
    float rb[8];   // B staging (fp32)

    auto loadA = [&](int p) {
        if (AHALF) {
            stA = aOk ? *reinterpret_cast<const uint4*>(aBaseH + p * 16)
                      : make_uint4(0, 0, 0, 0);
        } else {
            float la[8];
            if (aOk) {
                float4 a0 = *reinterpret_cast<const float4*>(aBaseF + p * 16);
                float4 a1 = *reinterpret_cast<const float4*>(aBaseF + p * 16 + 4);
                la[0] = a0.x; la[1] = a0.y; la[2] = a0.z; la[3] = a0.w;
                la[4] = a1.x; la[5] = a1.y; la[6] = a1.z; la[7] = a1.w;
            } else {
#pragma unroll
                for (int i = 0; i < 8; i++) la[i] = 0.f;
            }
            __half2 h0 = __floats2half2_rn(la[0], la[1]);
            __half2 h1 = __floats2half2_rn(la[2], la[3]);
            __half2 h2 = __floats2half2_rn(la[4], la[5]);
            __half2 h3 = __floats2half2_rn(la[6], la[7]);
            stA.x = *reinterpret_cast<unsigned*>(&h0);
            stA.y = *reinterpret_cast<unsigned*>(&h1);
            stA.z = *reinterpret_cast<unsigned*>(&h2);
            stA.w = *reinterpret_cast<unsigned*>(&h3);
        }
    };
    auto loadB = [&](int p) {
        const float* bp = bBase + (size_t)p * 16 * Ncols;
        if (bFull) {
            float4 b0 = *reinterpret_cast<const float4*>(bp);
            float4 b1 = *reinterpret_cast<const float4*>(bp + 4);
            rb[0] = b0.x; rb[1] = b0.y; rb[2] = b0.z; rb[3] = b0.w;
            rb[4] = b1.x; rb[5] = b1.y; rb[6] = b1.z; rb[7] = b1.w;
        } else {
#pragma unroll
            for (int j = 0; j < 8; j++)
                rb[j] = (gc + j < Ncols) ? bp[j] : 0.f;
        }
    };
    auto stsPanel = [&](int buf) {
        *reinterpret_cast<uint4*>(&smc[buf][aSts]) = stA;
        __half2 h0 = __floats2half2_rn(rb[0], rb[1]);
        __half2 h1 = __floats2half2_rn(rb[2], rb[3]);
        __half2 h2 = __floats2half2_rn(rb[4], rb[5]);
        __half2 h3 = __floats2half2_rn(rb[6], rb[7]);
        uint4 u;
        u.x = *reinterpret_cast<unsigned*>(&h0);
        u.y = *reinterpret_cast<unsigned*>(&h1);
        u.z = *reinterpret_cast<unsigned*>(&h2);
        u.w = *reinterpret_cast<unsigned*>(&h3);
        *reinterpret_cast<uint4*>(&smc[buf][bSts]) = u;
    };

    // prologue
    loadA(0); loadB(0);
    stsPanel(0);
    __syncthreads();

    for (int p = 0; p < P; p++) {
        int cur = p & 1, nxt = cur ^ 1;
        if (p + 1 < P) { loadA(p + 1); loadB(p + 1); }

        unsigned base = smBase + cur * 8192;
        unsigned af[4][4], bf[2][4];
#pragma unroll
        for (int mi = 0; mi < 4; mi++)
            ldmA4(af[mi][0], af[mi][1], af[mi][2], af[mi][3], base + aOff[mi]);
#pragma unroll
        for (int bi = 0; bi < 2; bi++)
            ldmBT4(bf[bi][0], bf[bi][1], bf[bi][2], bf[bi][3], base + bOff[bi]);

#pragma unroll
        for (int mi = 0; mi < 4; mi++)
#pragma unroll
            for (int ni = 0; ni < 4; ni++) {
                unsigned b0 = bf[ni >> 1][(ni & 1) * 2];
                unsigned b1 = bf[ni >> 1][(ni & 1) * 2 + 1];
                asm volatile(
                    "mma.sync.aligned.m16n8k16.row.col.f32.f16.f16.f32 "
                    "{%0,%1,%2,%3}, {%4,%5,%6,%7}, {%8,%9}, {%0,%1,%2,%3};\n"
                    : "+f"(acc[mi][ni][0]), "+f"(acc[mi][ni][1]),
                      "+f"(acc[mi][ni][2]), "+f"(acc[mi][ni][3])
                    : "r"(af[mi][0]), "r"(af[mi][1]), "r"(af[mi][2]), "r"(af[mi][3]),
                      "r"(b0), "r"(b1));
            }

        if (p + 1 < P) {
            __syncthreads();     // everyone done reading buf nxt from 2 panels ago
            stsPanel(nxt);
            __syncthreads();
        }
    }

    // store outputs
#pragma unroll
    for (int mi = 0; mi < 4; mi++) {
        int r0 = rowBase + warp_m * 64 + mi * 16 + gid;
#pragma unroll
        for (int ni = 0; ni < 4; ni++) {
            int c0 = colBase + warp_n * 32 + ni * 8 + tig * 2;
            if (c0 < Ncols) {
                if (r0 < M) {
                    *reinterpret_cast<__half2*>(&Ch[(size_t)r0 * Ncols + c0]) =
                        __floats2half2_rn(acc[mi][ni][0], acc[mi][ni][1]);
                    if (WF32)
                        *reinterpret_cast<float2*>(&C[(size_t)r0 * Ncols + c0]) =
                            make_float2(acc[mi][ni][0], acc[mi][ni][1]);
                }
                if (r0 + 8 < M) {
                    *reinterpret_cast<__half2*>(&Ch[(size_t)(r0 + 8) * Ncols + c0]) =
                        __floats2half2_rn(acc[mi][ni][2], acc[mi][ni][3]);
                    if (WF32)
                        *reinterpret_cast<float2*>(&C[(size_t)(r0 + 8) * Ncols + c0]) =
                            make_float2(acc[mi][ni][2], acc[mi][ni][3]);
                }
            }
        }
    }

    // fused el/er partials (heads 64 cols wide; warp's cols lie in one head)
    if (ATT) {
        int h = (colBase + warp_n * 32) >> 6;
#pragma unroll
        for (int mi = 0; mi < 4; mi++) {
            float pl0 = 0.f, pl1 = 0.f, pr0 = 0.f, pr1 = 0.f;
#pragma unroll
            for (int ni = 0; ni < 4; ni++) {
#pragma unroll
                for (int j = 0; j < 2; j++) {
                    int cw = (colBase + warp_n * 32 + ni * 8 + tig * 2 + j) & 63;
                    float av = al[h * 64 + cw];
                    float rv = ar[h * 64 + cw];
                    pl0 += acc[mi][ni][j] * av;
                    pr0 += acc[mi][ni][j] * rv;
                    pl1 += acc[mi][ni][2 + j] * av;
                    pr1 += acc[mi][ni][2 + j] * rv;
                }
            }
#pragma unroll
            for (int o = 1; o <= 2; o <<= 1) {
                pl0 += __shfl_xor_sync(0xffffffffu, pl0, o);
                pr0 += __shfl_xor_sync(0xffffffffu, pr0, o);
                pl1 += __shfl_xor_sync(0xffffffffu, pl1, o);
                pr1 += __shfl_xor_sync(0xffffffffu, pr1, o);
            }
            if (tig == 0) {
                int r0 = rowBase + warp_m * 64 + mi * 16 + gid;
                if (r0 < M) {
                    atomicAdd(&el[r0 * 4 + h], pl0);
                    atomicAdd(&er[r0 * 4 + h], pr0);
                }
                if (r0 + 8 < M) {
                    atomicAdd(&el[(r0 + 8) * 4 + h], pl1);
                    atomicAdd(&er[(r0 + 8) * 4 + h], pr1);
                }
            }
        }
    }
}

// -------- el/er for layer 2 (D=40, unaligned heads) — fp32 feat --------
__global__ void el_er_kernel(const float* __restrict__ feat,
                             const float* __restrict__ al, const float* __restrict__ ar,
                             float* __restrict__ el, float* __restrict__ er,
                             int N, int D) {
    int w = (blockIdx.x * blockDim.x + threadIdx.x) >> 5;
    int lane = threadIdx.x & 31;
    if (w >= N * HH) return;
    int n = w / HH, h = w - n * HH;
    const float* f = feat + (size_t)n * HH * D + h * D;
    float sl = 0.f, sr = 0.f;
    for (int d = lane; d < D; d += 32) {
        float fv = f[d];
        sl += fv * al[h * D + d];
        sr += fv * ar[h * D + d];
    }
#pragma unroll
    for (int o = 16; o; o >>= 1) {
        sl += __shfl_down_sync(0xffffffffu, sl, o);
        sr += __shfl_down_sync(0xffffffffu, sr, o);
    }
    if (lane == 0) { el[w] = sl; er[w] = sr; }
}

// 8 fp16 channels (uint4) fma into fp32 acc
__device__ __forceinline__ void hf8_fma(float* acc, uint4 u, float ee) {
    float2 f;
    f = __half22float2(*reinterpret_cast<__half2*>(&u.x));
    acc[0] += ee * f.x; acc[1] += ee * f.y;
    f = __half22float2(*reinterpret_cast<__half2*>(&u.y));
    acc[2] += ee * f.x; acc[3] += ee * f.y;
    f = __half22float2(*reinterpret_cast<__half2*>(&u.z));
    acc[4] += ee * f.x; acc[5] += ee * f.y;
    f = __half22float2(*reinterpret_cast<__half2*>(&u.w));
    acc[6] += ee * f.x; acc[7] += ee * f.y;
}

// -------- fused softmax + aggregation: one warp per dst node --------
// Global-per-head softmax shift (no per-node max pass).
// MODE 0: D=64, out fp16 [d,256] = elu(acc/den + bias)
// MODE 1: D=40, lanes 0..19, out fp32 logits[d,40] = mean_h(acc/den + bias)
template <int D, int MODE>
__global__ __launch_bounds__(256) void gat_aggregate(
    const int* __restrict__ rowptr, const int* __restrict__ srcS,
    const float* __restrict__ el, const float* __restrict__ er,
    const unsigned* __restrict__ gmax,
    const __half* __restrict__ hfeat, const float* __restrict__ bias,
    __half* __restrict__ outH, float* __restrict__ outF, int N) {
    constexpr int HD = 4 * D;
    __shared__ float sEE[8][4][32];
    __shared__ int sSrc[8][32];
    __shared__ float sOut[MODE == 1 ? 8 : 1][MODE == 1 ? 160 : 1];
    int wl = threadIdx.x >> 5, lane = threadIdx.x & 31;
    int d = blockIdx.x * 8 + wl;
    if (d >= N) return;
    int begin = rowptr[d], end = rowptr[d + 1];

    float4 erv = *reinterpret_cast<const float4*>(&er[d * 4]);
    float er4[4] = {erv.x, erv.y, erv.z, erv.w};

    // softmax shift from global per-head el max (upper bound of per-node max)
    float m[4];
#pragma unroll
    for (int h = 0; h < 4; h++) {
        float v = fdecode(gmax[h]) + er4[h];
        m[h] = v > 0.f ? v : 0.2f * v;
    }

    float acc[8];
#pragma unroll
    for (int j = 0; j < 8; j++) acc[j] = 0.f;
    float den[4] = {0.f, 0.f, 0.f, 0.f};

    const int h = (MODE == 0) ? (lane >> 3) : (lane / 5);
    const bool active = (MODE == 0) ? true : (lane < 20);
    const int cOff = lane * 8;

    for (int base = begin; base < end; base += 32) {
        int cnt = min(32, end - base);
        if (lane < cnt) {
            int s = srcS[base + lane];
            sSrc[wl][lane] = s;
            float4 e4 = *reinterpret_cast<const float4*>(&el[s * 4]);
            float v, ee;
            v = e4.x + er4[0]; v = v > 0.f ? v : 0.2f * v; ee = __expf(v - m[0]); den[0] += ee; sEE[wl][0][lane] = ee;
            v = e4.y + er4[1]; v = v > 0.f ? v : 0.2f * v; ee = __expf(v - m[1]); den[1] += ee; sEE[wl][1][lane] = ee;
            v = e4.z + er4[2]; v = v > 0.f ? v : 0.2f * v; ee = __expf(v - m[2]); den[2] += ee; sEE[wl][2][lane] = ee;
            v = e4.w + er4[3]; v = v > 0.f ? v : 0.2f * v; ee = __expf(v - m[3]); den[3] += ee; sEE[wl][3][lane] = ee;
        }
        __syncwarp();

        if (active) {
            int t = 0;
            for (; t + 3 < cnt; t += 4) {
                int s0 = sSrc[wl][t], s1 = sSrc[wl][t + 1], s2 = sSrc[wl][t + 2], s3 = sSrc[wl][t + 3];
                uint4 u0 = *reinterpret_cast<const uint4*>(hfeat + (size_t)s0 * HD + cOff);
                uint4 u1 = *reinterpret_cast<const uint4*>(hfeat + (size_t)s1 * HD + cOff);
                uint4 u2 = *reinterpret_cast<const uint4*>(hfeat + (size_t)s2 * HD + cOff);
                uint4 u3 = *reinterpret_cast<const uint4*>(hfeat + (size_t)s3 * HD + cOff);
                hf8_fma(acc, u0, sEE[wl][h][t]);
                hf8_fma(acc, u1, sEE[wl][h][t + 1]);
                hf8_fma(acc, u2, sEE[wl][h][t + 2]);
                hf8_fma(acc, u3, sEE[wl][h][t + 3]);
            }
            for (; t < cnt; t++) {
                int s0 = sSrc[wl][t];
                uint4 u0 = *reinterpret_cast<const uint4*>(hfeat + (size_t)s0 * HD + cOff);
                hf8_fma(acc, u0, sEE[wl][h][t]);
            }
        }
        __syncwarp();
    }

#pragma unroll
    for (int hh = 0; hh < 4; hh++) {
#pragma unroll
        for (int o = 16; o; o >>= 1)
            den[hh] += __shfl_xor_sync(0xffffffffu, den[hh], o);
        den[hh] = fmaxf(den[hh], 1e-30f);
    }

    if constexpr (MODE == 0) {
        float inv = 1.f / den[h];
        uint4 u;
        unsigned* up = &u.x;
#pragma unroll
        for (int j = 0; j < 4; j++) {
            float v0 = acc[2 * j] * inv + bias[cOff + 2 * j];
            float v1 = acc[2 * j + 1] * inv + bias[cOff + 2 * j + 1];
            v0 = v0 > 0.f ? v0 : expm1f(v0);
            v1 = v1 > 0.f ? v1 : expm1f(v1);
            __half2 hh2 = __floats2half2_rn(v0, v1);
            up[j] = *reinterpret_cast<unsigned*>(&hh2);
        }
        *reinterpret_cast<uint4*>(outH + (size_t)d * 256 + cOff) = u;
    } else {
        if (active) {
            float inv = 1.f / den[h];
#pragma unroll
            for (int j = 0; j < 8; j++)
                sOut[wl][cOff + j] = acc[j] * inv + bias[cOff + j];
        }
        __syncwarp();
        float* lg = outF + (size_t)d * 40;
        {
            int c = lane;
            lg[c] = 0.25f * (sOut[wl][c] + sOut[wl][40 + c] + sOut[wl][80 + c] + sOut[wl][120 + c]);
        }
        if (lane < 8) {
            int c = 32 + lane;
            lg[c] = 0.25f * (sOut[wl][c] + sOut[wl][40 + c] + sOut[wl][80 + c] + sOut[wl][120 + c]);
        }
    }
}

// ---------------------------------------------------------------
extern "C" void kernel_launch(void* const* d_in, const int* in_sizes, int n_in,
                              void* d_out, int out_size) {
    const float* x  = (const float*)d_in[0];
    const int*   ei = (const int*)d_in[1];
    const float* W0  = (const float*)d_in[2];
    const float* al0 = (const float*)d_in[3];
    const float* ar0 = (const float*)d_in[4];
    const float* b0  = (const float*)d_in[5];
    const float* W1  = (const float*)d_in[6];
    const float* al1 = (const float*)d_in[7];
    const float* ar1 = (const float*)d_in[8];
    const float* b1  = (const float*)d_in[9];
    const float* W2  = (const float*)d_in[10];
    const float* al2 = (const float*)d_in[11];
    const float* ar2 = (const float*)d_in[12];
    const float* b2  = (const float*)d_in[13];

    int E = in_sizes[1] / 2;
    int N = in_sizes[0] / 256;
    const int* src = ei;
    const int* dst = ei + E;

    void* hv = nullptr;
    cudaGetSymbolAddress(&hv, g_hf);
    __half* hfeat = (__half*)hv;
    __half* bufA  = hfeat + (size_t)NN * 256;
    __half* bufB  = bufA + (size_t)NN * 256;

    void* pv = nullptr;
    cudaGetSymbolAddress(&pv, g_pool);
    float* feat = (float*)pv;                        // fp32 feat (layer 2 only)
    float* el   = feat + (size_t)NN * 256;
    float* er   = el + (size_t)NN * 4;

    void* iv = nullptr;
    cudaGetSymbolAddress(&iv, g_ipool);
    int* rowptr = (int*)iv;
    int* deg    = rowptr + NN + 1;
    int* cursor = deg + NN;
    int* srcS   = cursor + NN;
    unsigned* gmax = (unsigned*)(srcS + EE);

    const int TB = 256;
    auto blocks = [](long n, int tb) { return (int)((n + tb - 1) / tb); };

    // ---- build CSR (by dst) ----
    zero_int<<<blocks(N, TB), TB>>>(deg, N);
    hist_kernel<<<blocks(E, TB), TB>>>(dst, deg, E);
    scan_kernel<<<1, 1024>>>(deg, rowptr, cursor, N, E);
    scatter_kernel<<<blocks(E, TB), TB>>>(src, dst, cursor, srcS, E);

    int aggBlocks = (N + 7) / 8;
    int gy = (N + 127) / 128;

    // ---- layer 0: x (fp32) -> bufA (fp16) ----
    zero_att<<<blocks((long)N * 8, TB), TB>>>(el, gmax, N * 8);
    gemm_fp16<true, false, false><<<dim3(2, gy), 256>>>(x, nullptr, W0, nullptr, hfeat,
                                                        N, 256, 256, al0, ar0, el, er);
    gmax_kernel<<<128, 256>>>(el, gmax, N * 4);
    gat_aggregate<64, 0><<<aggBlocks, 256>>>(rowptr, srcS, el, er, gmax, hfeat, b0, bufA, nullptr, N);

    // ---- layer 1: bufA (fp16) -> bufB (fp16) ----
    zero_att<<<blocks((long)N * 8, TB), TB>>>(el, gmax, N * 8);
    gemm_fp16<true, false, true><<<dim3(2, gy), 256>>>(nullptr, bufA, W1, nullptr, hfeat,
                                                       N, 256, 256, al1, ar1, el, er);
    gmax_kernel<<<128, 256>>>(el, gmax, N * 4);
    gat_aggregate<64, 0><<<aggBlocks, 256>>>(rowptr, srcS, el, er, gmax, hfeat, b1, bufB, nullptr, N);

    // ---- layer 2: bufB (fp16) -> logits ----
    gemm_fp16<false, true, true><<<dim3(2, gy), 256>>>(nullptr, bufB, W2, feat, hfeat,
                                                       N, 256, 160, nullptr, nullptr, nullptr, nullptr);
    el_er_kernel<<<blocks((long)N * HH * 32, TB), TB>>>(feat, al2, ar2, el, er, N, 40);
    zero_int<<<1, 32>>>((int*)gmax, 4);
    gmax_kernel<<<128, 256>>>(el, gmax, N * 4);
    gat_aggregate<40, 1><<<aggBlocks, 256>>>(rowptr, srcS, el, er, gmax, hfeat, b2, nullptr, (float*)d_out, N);
}